// round 17
// baseline (speedup 1.0000x reference)
#include <cuda_runtime.h>
#include <cuda_bf16.h>
#include <cstdint>

#define NUM_GRAPHS 512
#define C 128
#define CG (C / 4)            // 32 channel-groups of float4
#define THREADS 1024
#define RPI (THREADS / CG)    // 32 rows per iteration
#define EPS 1e-5f
#define GRID 148
#define NCLUST (GRID / 4)     // 37 persistent clusters of 4
#define MAXLOC 14             // ceil(512/37)
#define CAP 320               // buffered rows per CTA (quarter max ~275)

// dynamic smem layout (bytes)
#define OFF_BUF   0
#define SZ_BUF    (CAP * C * 4)            // 163840
#define OFF_SUM   (OFF_BUF + SZ_BUF)       // 163840
#define SZ_SUM    (RPI * C * 4)            // 16384
#define OFF_SQ    (OFF_SUM + SZ_SUM)       // 180224
#define OFF_PART  (OFF_SQ + SZ_SUM)        // 196608  [2][C] own partials
#define OFF_MI    (OFF_PART + 2 * C * 4)   // 197632  [2][C] mean|inv
#define OFF_BOUND (OFF_MI + 2 * C * 4)     // 198656  bounds
#define SMEM_TOTAL (OFF_BOUND + 2 * MAXLOC * 4 + 16)

extern __shared__ __align__(16) unsigned char dsm[];

__device__ __forceinline__ uint32_t smem_u32(const void* p) {
    uint32_t a;
    asm("{ .reg .u64 t; cvta.to.shared.u64 t, %1; cvt.u32.u64 %0, t; }"
        : "=r"(a) : "l"(p));
    return a;
}
__device__ __forceinline__ uint32_t mapa_rank(uint32_t addr, uint32_t rank) {
    uint32_t r;
    asm("mapa.shared::cluster.u32 %0, %1, %2;" : "=r"(r) : "r"(addr), "r"(rank));
    return r;
}
__device__ __forceinline__ void ld_dsmem_v4(uint32_t addr, float& a, float& b,
                                            float& c, float& d) {
    asm volatile("ld.shared::cluster.v4.f32 {%0,%1,%2,%3}, [%4];"
                 : "=f"(a), "=f"(b), "=f"(c), "=f"(d) : "r"(addr));
}
__device__ __forceinline__ uint32_t my_ctarank() {
    uint32_t r;
    asm("mov.u32 %0, %%cluster_ctarank;" : "=r"(r));
    return r;
}
#define CLUSTER_SYNC() do { \
    asm volatile("barrier.cluster.arrive.aligned;" ::: "memory"); \
    asm volatile("barrier.cluster.wait.aligned;"   ::: "memory"); } while (0)

// Interpolation-guess + gallop: first idx with batch[idx] >= g.
__device__ __forceinline__ int find_bound(const int* __restrict__ batch, int n, int g) {
    if (g <= 0) return 0;
    if (g >= NUM_GRAPHS) return n;
    int p = (int)(((long long)g * (long long)n) >> 9);
    if (p > n) p = n;
    int wlo = p, s = 512;
    while (wlo > 0 && batch[wlo - 1] >= g) { wlo -= s; if (wlo < 0) wlo = 0; s <<= 1; }
    int whi = p; s = 512;
    while (whi < n && batch[whi] < g)      { whi += s; if (whi > n) whi = n; s <<= 1; }
    while (wlo < whi) {
        int mid = (wlo + whi) >> 1;
        if (batch[mid] < g) wlo = mid + 1; else whi = mid;
    }
    return wlo;
}

#define ACC(v) do { \
    s0 += (v).x; s1 += (v).y; s2 += (v).z; s3 += (v).w; \
    q0 += (v).x * (v).x; q1 += (v).y * (v).y; \
    q2 += (v).z * (v).z; q3 += (v).w * (v).w; } while (0)

__global__ __launch_bounds__(THREADS, 1) __cluster_dims__(4, 1, 1)
void graphnorm_kernel(const float* __restrict__ x,
                      const int*   __restrict__ batch,
                      const float* __restrict__ weight,
                      const float* __restrict__ bias,
                      float* __restrict__ out,
                      int n) {
    const int t    = threadIdx.x;
    const int cg   = t & (CG - 1);
    const int rw   = t >> 5;               // 0..31
    const int rank = (int)my_ctarank();    // 0..3 within cluster
    const int cid  = blockIdx.x >> 2;      // cluster id 0..36

    float4* buff4    = (float4*)(dsm + OFF_BUF);   // [CAP][CG]
    float*  s_sum    = (float* )(dsm + OFF_SUM);   // [RPI][C]
    float*  s_sq     = (float* )(dsm + OFF_SQ);    // [RPI][C]
    float*  part     = (float* )(dsm + OFF_PART);  // [2][C]
    float*  meaninv  = (float* )(dsm + OFF_MI);    // [2][C]
    int*    s_bound  = (int*  )(dsm + OFF_BOUND);

    // local segment list: seg = cid + i*NCLUST
    const int nloc = (NUM_GRAPHS - 1 - cid) / NCLUST + 1;

    // ---- precompute ALL bounds in parallel (one gallop latency total) ----
    if (t < 2 * nloc) {
        const int g = cid + (t >> 1) * NCLUST + (t & 1);
        s_bound[t] = find_bound(batch, n, g);
    }

    const float4 wv = ((const float4*)weight)[cg];
    const float4 bv = ((const float4*)bias)[cg];
    const float4* __restrict__ xp = (const float4*)x;
    float4* __restrict__       op = (float4*)out;

    const uint32_t part_addr = smem_u32(part);

    __syncthreads();
    CLUSTER_SYNC();

    for (int i = 0; i < nloc; i++) {
        const int st  = s_bound[2 * i];
        const int en  = s_bound[2 * i + 1];
        const int cnt = en - st;
        const int qlo = st + ((cnt * rank) >> 2);         // my quarter
        const int qhi = st + ((cnt * (rank + 1)) >> 2);
        const int qcnt = qhi - qlo;
        const int nbuf = qcnt < CAP ? qcnt : CAP;         // rows that fit in smem

        // ---- pass 1: single DRAM read; ACC + stash into smem ----
        float s0 = 0.f, s1 = 0.f, s2 = 0.f, s3 = 0.f;
        float q0 = 0.f, q1 = 0.f, q2 = 0.f, q3 = 0.f;
        int lr = rw;
        for (; lr + 3 * RPI < qcnt; lr += 4 * RPI) {
            float4 a = __ldcg(&xp[(size_t)(qlo + lr          ) * CG + cg]);
            float4 b = __ldcg(&xp[(size_t)(qlo + lr + 1 * RPI) * CG + cg]);
            float4 c = __ldcg(&xp[(size_t)(qlo + lr + 2 * RPI) * CG + cg]);
            float4 d = __ldcg(&xp[(size_t)(qlo + lr + 3 * RPI) * CG + cg]);
            ACC(a); ACC(b); ACC(c); ACC(d);
            if (lr           < nbuf) buff4[(lr          ) * CG + cg] = a;
            if (lr + 1 * RPI < nbuf) buff4[(lr + 1 * RPI) * CG + cg] = b;
            if (lr + 2 * RPI < nbuf) buff4[(lr + 2 * RPI) * CG + cg] = c;
            if (lr + 3 * RPI < nbuf) buff4[(lr + 3 * RPI) * CG + cg] = d;
        }
        for (; lr < qcnt; lr += RPI) {
            float4 v = __ldcg(&xp[(size_t)(qlo + lr) * CG + cg]);
            ACC(v);
            if (lr < nbuf) buff4[lr * CG + cg] = v;
        }
        s_sum[rw * C + cg * 4 + 0] = s0; s_sum[rw * C + cg * 4 + 1] = s1;
        s_sum[rw * C + cg * 4 + 2] = s2; s_sum[rw * C + cg * 4 + 3] = s3;
        s_sq [rw * C + cg * 4 + 0] = q0; s_sq [rw * C + cg * 4 + 1] = q1;
        s_sq [rw * C + cg * 4 + 2] = q2; s_sq [rw * C + cg * 4 + 3] = q3;
        __syncthreads();

        // ---- local reduce -> own quarter partials (threads 0..31, fixed order) ----
        if (t < CG) {
            float S0 = 0.f, S1 = 0.f, S2 = 0.f, S3 = 0.f;
            float Q0 = 0.f, Q1 = 0.f, Q2 = 0.f, Q3 = 0.f;
            #pragma unroll
            for (int k = 0; k < RPI; k++) {
                S0 += s_sum[k * C + t * 4 + 0]; S1 += s_sum[k * C + t * 4 + 1];
                S2 += s_sum[k * C + t * 4 + 2]; S3 += s_sum[k * C + t * 4 + 3];
                Q0 += s_sq [k * C + t * 4 + 0]; Q1 += s_sq [k * C + t * 4 + 1];
                Q2 += s_sq [k * C + t * 4 + 2]; Q3 += s_sq [k * C + t * 4 + 3];
            }
            ((float4*)part)[t]      = make_float4(S0, S1, S2, S3);
            ((float4*)(part + C))[t] = make_float4(Q0, Q1, Q2, Q3);
        }
        __syncthreads();       // drain partial STS before peers read
        CLUSTER_SYNC();        // all 4 CTAs' partials visible cluster-wide

        // ---- all-gather partials rank-order (bit-identical in all CTAs) ----
        if (t < CG) {
            float S0 = 0.f, S1 = 0.f, S2 = 0.f, S3 = 0.f;
            float Q0 = 0.f, Q1 = 0.f, Q2 = 0.f, Q3 = 0.f;
            #pragma unroll
            for (int r = 0; r < 4; r++) {
                const uint32_t pb = mapa_rank(part_addr, (uint32_t)r);
                float a0, a1, a2, a3;
                ld_dsmem_v4(pb + (uint32_t)t * 16u, a0, a1, a2, a3);
                S0 += a0; S1 += a1; S2 += a2; S3 += a3;
                ld_dsmem_v4(pb + (uint32_t)(C * 4) + (uint32_t)t * 16u,
                            a0, a1, a2, a3);
                Q0 += a0; Q1 += a1; Q2 += a2; Q3 += a3;
            }
            const float invc = 1.0f / (float)max(cnt, 1);
            float m0 = S0 * invc, m1 = S1 * invc, m2 = S2 * invc, m3 = S3 * invc;
            ((float4*)meaninv)[t] = make_float4(m0, m1, m2, m3);
            ((float4*)(meaninv + C))[t] = make_float4(
                rsqrtf(Q0 * invc - m0 * m0 + EPS),
                rsqrtf(Q1 * invc - m1 * m1 + EPS),
                rsqrtf(Q2 * invc - m2 * m2 + EPS),
                rsqrtf(Q3 * invc - m3 * m3 + EPS));
        }
        __syncthreads();

        const float4 m  = ((const float4*)meaninv)[cg];
        const float4 iv = ((const float4*)(meaninv + C))[cg];

        // ---- pass 2: normalize from SMEM (no DRAM loads); streaming stores ----
        for (lr = rw; lr < qcnt; lr += RPI) {
            float4 v = (lr < nbuf) ? buff4[lr * CG + cg]
                                   : __ldcg(&xp[(size_t)(qlo + lr) * CG + cg]);
            v.x = (v.x - m.x) * iv.x * wv.x + bv.x;
            v.y = (v.y - m.y) * iv.y * wv.y + bv.y;
            v.z = (v.z - m.z) * iv.z * wv.z + bv.z;
            v.w = (v.w - m.w) * iv.w * wv.w + bv.w;
            __stcs(&op[(size_t)(qlo + lr) * CG + cg], v);
        }

        CLUSTER_SYNC();   // full barrier: buf/part safe to overwrite next iter
    }
}

extern "C" void kernel_launch(void* const* d_in, const int* in_sizes, int n_in,
                              void* d_out, int out_size) {
    const float* x      = (const float*)d_in[0];
    const int*   batch  = (const int*)d_in[1];
    const float* weight = (const float*)d_in[2];
    const float* bias   = (const float*)d_in[3];
    float*       out    = (float*)d_out;
    const int n = in_sizes[1];

    cudaFuncSetAttribute(graphnorm_kernel,
                         cudaFuncAttributeMaxDynamicSharedMemorySize, SMEM_TOTAL);
    graphnorm_kernel<<<GRID, THREADS, SMEM_TOTAL>>>(x, batch, weight, bias, out, n);
}